// round 1
// baseline (speedup 1.0000x reference)
#include <cuda_runtime.h>
#include <math.h>

#define NPTS 3072
#define NOUT 16

__global__ __launch_bounds__(256) void sparse_edge_kernel(
    const float* __restrict__ coord,
    const float* __restrict__ sig,
    float* __restrict__ out)
{
    __shared__ float s_inv[NOUT];   // 1/(2*sigma_c^2), rounded like the reference
    __shared__ float s_qden;        // 2*sigma_max*sigma_max

    if (threadIdx.x < NOUT) {
        float s = sig[threadIdx.x];
        // reference: 1.0 / (2.0 * sigma * sigma)  -> ((2*s)*s), then fp32 divide
        s_inv[threadIdx.x] = __fdiv_rn(1.0f, __fmul_rn(__fmul_rn(2.0f, s), s));
    }
    if (threadIdx.x == 0) {
        float sm = sig[NOUT - 1];
        s_qden = __fmul_rn(__fmul_rn(2.0f, sm), sm);
    }
    __syncthreads();

    const int j = blockIdx.x * blockDim.x + threadIdx.x;
    const int i = blockIdx.y;
    if (j >= NPTS) return;

    const float xi = __ldg(coord + 3 * i + 0);
    const float yi = __ldg(coord + 3 * i + 1);
    const float zi = __ldg(coord + 3 * i + 2);
    const float xj = __ldg(coord + 3 * j + 0);
    const float yj = __ldg(coord + 3 * j + 1);
    const float zj = __ldg(coord + 3 * j + 2);

    // sq = (x*x + y*y) + z*z, no fma contraction (matches XLA reduce order)
    const float sqi = __fadd_rn(__fadd_rn(__fmul_rn(xi, xi), __fmul_rn(yi, yi)),
                                __fmul_rn(zi, zi));
    const float sqj = __fadd_rn(__fadd_rn(__fmul_rn(xj, xj), __fmul_rn(yj, yj)),
                                __fmul_rn(zj, zj));
    // dot via ascending-k fma chain (Eigen gebp on aarch64 uses fused madd)
    const float dot = __fmaf_rn(zi, zj, __fmaf_rn(yi, yj, __fmul_rn(xi, xj)));

    float d2 = __fsub_rn(__fadd_rn(sqi, sqj), __fmul_rn(2.0f, dot));
    d2 = fmaxf(d2, 0.0f);

    // keep = (exp(-d2/(2*smax^2)) >= 0.9) && d2 > 0 && i != j
    bool keep = false;
    if (d2 > 0.0f && i != j) {
        const float q = __fdiv_rn(d2, s_qden);
        // exact boundary in q is -ln(0.9f - 0.5ulp) ~= 0.10536058
        if (q <= 0.105340f) {
            keep = true;
        } else if (q >= 0.105380f) {
            keep = false;
        } else {
            // rare boundary band: correctly-rounded fp32 exp via double
            const float ef = (float)exp(-(double)q);
            keep = (ef >= 0.9f);
        }
    }

    float4 r0 = make_float4(0.f, 0.f, 0.f, 0.f);
    float4 r1 = r0, r2 = r0, r3 = r0;

    if (keep) {
        float v[NOUT];
#pragma unroll
        for (int c = 0; c < NOUT; c++) {
            // reference: exp(-(d2 * inv_two_sig2[c]))
            v[c] = __expf(-__fmul_rn(d2, s_inv[c]));
        }
        r0 = make_float4(v[0],  v[1],  v[2],  v[3]);
        r1 = make_float4(v[4],  v[5],  v[6],  v[7]);
        r2 = make_float4(v[8],  v[9],  v[10], v[11]);
        r3 = make_float4(v[12], v[13], v[14], v[15]);
    }

    float4* base = reinterpret_cast<float4*>(out + ((size_t)i * NPTS + j) * NOUT);
    base[0] = r0;
    base[1] = r1;
    base[2] = r2;
    base[3] = r3;
}

extern "C" void kernel_launch(void* const* d_in, const int* in_sizes, int n_in,
                              void* d_out, int out_size)
{
    const float* coord = (const float*)d_in[0];   // [3072, 3] fp32
    const float* sig   = (const float*)d_in[1];   // [16] fp32
    float* out = (float*)d_out;                   // [1, 3072, 3072, 16] fp32

    dim3 block(256);
    dim3 grid((NPTS + 255) / 256, NPTS);
    sparse_edge_kernel<<<grid, block>>>(coord, sig, out);
}

// round 2
// speedup vs baseline: 1.1835x; 1.1835x over previous
#include <cuda_runtime.h>
#include <math.h>

#define NPTS 3072
#define NOUT 16

// Sparse fill: write ONLY the kept entries (~2.9% of pairs), 64 B each.
// Bulk zeros are handled by cudaMemsetAsync before this kernel.
__global__ __launch_bounds__(256) void sparse_fill_kernel(
    const float* __restrict__ coord,
    const float* __restrict__ sig,
    float* __restrict__ out)
{
    __shared__ float s_inv[NOUT];   // 1/(2*sigma_c^2), rounded like the reference
    __shared__ float s_qden;        // 2*sigma_max*sigma_max

    if (threadIdx.x < NOUT) {
        float s = sig[threadIdx.x];
        s_inv[threadIdx.x] = __fdiv_rn(1.0f, __fmul_rn(__fmul_rn(2.0f, s), s));
    }
    if (threadIdx.x == 0) {
        float sm = sig[NOUT - 1];
        s_qden = __fmul_rn(__fmul_rn(2.0f, sm), sm);
    }
    __syncthreads();

    const int j = blockIdx.x * blockDim.x + threadIdx.x;
    const int i = blockIdx.y;
    if (j >= NPTS) return;

    const float xi = __ldg(coord + 3 * i + 0);
    const float yi = __ldg(coord + 3 * i + 1);
    const float zi = __ldg(coord + 3 * i + 2);
    const float xj = __ldg(coord + 3 * j + 0);
    const float yj = __ldg(coord + 3 * j + 1);
    const float zj = __ldg(coord + 3 * j + 2);

    // sq = (x*x + y*y) + z*z, no fma contraction (matches XLA reduce order)
    const float sqi = __fadd_rn(__fadd_rn(__fmul_rn(xi, xi), __fmul_rn(yi, yi)),
                                __fmul_rn(zi, zi));
    const float sqj = __fadd_rn(__fadd_rn(__fmul_rn(xj, xj), __fmul_rn(yj, yj)),
                                __fmul_rn(zj, zj));
    // dot via ascending-k fma chain (matches host fma path)
    const float dot = __fmaf_rn(zi, zj, __fmaf_rn(yi, yj, __fmul_rn(xi, xj)));

    float d2 = __fsub_rn(__fadd_rn(sqi, sqj), __fmul_rn(2.0f, dot));
    d2 = fmaxf(d2, 0.0f);

    // keep = (exp(-d2/(2*smax^2)) >= 0.9) && d2 > 0 && i != j
    bool keep = false;
    if (d2 > 0.0f && i != j) {
        const float q = __fdiv_rn(d2, s_qden);
        if (q <= 0.105340f) {
            keep = true;
        } else if (q >= 0.105380f) {
            keep = false;
        } else {
            // rare boundary band: correctly-rounded fp32 exp via double
            const float ef = (float)exp(-(double)q);
            keep = (ef >= 0.9f);
        }
    }

    if (keep) {
        float v[NOUT];
#pragma unroll
        for (int c = 0; c < NOUT; c++) {
            v[c] = __expf(-__fmul_rn(d2, s_inv[c]));
        }
        float4* base = reinterpret_cast<float4*>(out + ((size_t)i * NPTS + j) * NOUT);
        base[0] = make_float4(v[0],  v[1],  v[2],  v[3]);
        base[1] = make_float4(v[4],  v[5],  v[6],  v[7]);
        base[2] = make_float4(v[8],  v[9],  v[10], v[11]);
        base[3] = make_float4(v[12], v[13], v[14], v[15]);
    }
}

extern "C" void kernel_launch(void* const* d_in, const int* in_sizes, int n_in,
                              void* d_out, int out_size)
{
    const float* coord = (const float*)d_in[0];   // [3072, 3] fp32
    const float* sig   = (const float*)d_in[1];   // [16] fp32
    float* out = (float*)d_out;                   // [1, 3072, 3072, 16] fp32

    // Bulk zeros via the driver's tuned memset (graph-capturable memset node).
    cudaMemsetAsync(d_out, 0, (size_t)NPTS * NPTS * NOUT * sizeof(float), 0);

    // Then write only the kept entries on top.
    dim3 block(256);
    dim3 grid((NPTS + 255) / 256, NPTS);
    sparse_fill_kernel<<<grid, block>>>(coord, sig, out);
}

// round 3
// speedup vs baseline: 1.3877x; 1.1725x over previous
#include <cuda_runtime.h>
#include <math.h>

#define NPTS 3072
#define NOUT 16
#define TI 32          // i-rows per block
#define TJ 256         // j-cols per block (= blockDim.x)
#define CAP 1280       // smem edge buffer capacity per tile

__global__ __launch_bounds__(256) void sparse_fill_kernel(
    const float* __restrict__ coord,
    const float* __restrict__ sig,
    float* __restrict__ out)
{
    __shared__ float4 s_i[TI];          // xi, yi, zi, sqi
    __shared__ float  s_inv[NOUT];      // 1/(2*sigma_c^2), reference rounding
    __shared__ float  s_qden, s_lo, s_hi;
    __shared__ unsigned s_cnt;
    __shared__ float    s_ed2[CAP];
    __shared__ unsigned s_eidx[CAP];

    const int tid    = threadIdx.x;
    const int j_base = blockIdx.x * TJ;
    const int i_base = blockIdx.y * TI;
    const int j      = j_base + tid;

    if (tid < NOUT) {
        float s = sig[tid];
        s_inv[tid] = __fdiv_rn(1.0f, __fmul_rn(__fmul_rn(2.0f, s), s));
    }
    if (tid == 0) {
        float sm = sig[NOUT - 1];
        float qd = __fmul_rn(__fmul_rn(2.0f, sm), sm);
        s_qden = qd;
        s_lo = 0.105300f * qd;   // conservative fast-keep bound
        s_hi = 0.105420f * qd;   // conservative fast-drop bound
        s_cnt = 0u;
    }
    if (tid < TI) {
        int ig = i_base + tid;
        float x = coord[3 * ig + 0];
        float y = coord[3 * ig + 1];
        float z = coord[3 * ig + 2];
        float sq = __fadd_rn(__fadd_rn(__fmul_rn(x, x), __fmul_rn(y, y)),
                             __fmul_rn(z, z));
        s_i[tid] = make_float4(x, y, z, sq);
    }

    // j-coords for this thread (register-resident across the whole i-loop)
    const float xj = coord[3 * j + 0];
    const float yj = coord[3 * j + 1];
    const float zj = coord[3 * j + 2];
    const float sqj = __fadd_rn(__fadd_rn(__fmul_rn(xj, xj), __fmul_rn(yj, yj)),
                                __fmul_rn(zj, zj));
    __syncthreads();

    const float lo = s_lo, hi = s_hi, qden = s_qden;

#pragma unroll 4
    for (int ii = 0; ii < TI; ii++) {
        const float4 I = s_i[ii];
        const float dot = __fmaf_rn(I.z, zj, __fmaf_rn(I.y, yj, __fmul_rn(I.x, xj)));
        float d2 = __fsub_rn(__fadd_rn(I.w, sqj), __fmul_rn(2.0f, dot));
        d2 = fmaxf(d2, 0.0f);

        bool keep;
        if (d2 <= lo) {
            keep = (d2 > 0.0f) && ((i_base + ii) != j);
        } else if (d2 >= hi) {
            keep = false;
        } else {
            // boundary band: reproduce reference predicate exactly
            const float q = __fdiv_rn(d2, qden);
            if (q <= 0.105340f)       keep = true;
            else if (q >= 0.105380f)  keep = false;
            else                      keep = ((float)exp(-(double)q) >= 0.9f);
            keep = keep && (d2 > 0.0f) && ((i_base + ii) != j);
        }

        if (keep) {
            unsigned slot = atomicAdd(&s_cnt, 1u);
            if (slot < CAP) {
                s_ed2[slot]  = d2;
                s_eidx[slot] = ((unsigned)ii << 8) | (unsigned)tid;
            } else {
                // overflow fallback (effectively unreachable): write inline
                float* base = out + ((size_t)(i_base + ii) * NPTS + j) * NOUT;
#pragma unroll
                for (int c = 0; c < NOUT; c++)
                    base[c] = __expf(-__fmul_rn(d2, s_inv[c]));
            }
        }
    }

    __syncthreads();

    // Dense flush: 16 threads per edge, one channel each.
    const int cnt = (int)min(s_cnt, (unsigned)CAP);
    const int c   = tid & (NOUT - 1);
    const float invc = s_inv[c];
    for (int e = tid >> 4; e < cnt; e += (TJ / NOUT)) {
        const float    d2 = s_ed2[e];
        const unsigned p  = s_eidx[e];
        const int ii = (int)(p >> 8);
        const int jl = (int)(p & 255u);
        const float v = __expf(-__fmul_rn(d2, invc));
        out[((size_t)(i_base + ii) * NPTS + (j_base + jl)) * NOUT + c] = v;
    }
}

extern "C" void kernel_launch(void* const* d_in, const int* in_sizes, int n_in,
                              void* d_out, int out_size)
{
    const float* coord = (const float*)d_in[0];   // [3072, 3] fp32
    const float* sig   = (const float*)d_in[1];   // [16] fp32
    float* out = (float*)d_out;                   // [1, 3072, 3072, 16] fp32

    // Bulk zeros at the HBM write roofline (graph memset node).
    cudaMemsetAsync(d_out, 0, (size_t)NPTS * NPTS * NOUT * sizeof(float), 0);

    dim3 block(TJ);
    dim3 grid(NPTS / TJ, NPTS / TI);   // (12, 96)
    sparse_fill_kernel<<<grid, block>>>(coord, sig, out);
}